// round 7
// baseline (speedup 1.0000x reference)
#include <cuda_runtime.h>
#include <math.h>

// ---------------- problem constants ----------------
constexpr int Nn  = 50000;
constexpr int Ee  = 800000;
constexpr int ET  = Ee + Nn;          // 850000
constexpr int Hh  = 4;
constexpr int Cc  = 16;
constexpr int F   = Hh * Cc;          // 64
constexpr int IND = 128;
constexpr int NGr = 128;
constexpr float NEG   = 0.2f;
constexpr float EPSbn = 1e-5f;
constexpr int NBLK = (Nn + 255) / 256;  // 196 scan blocks

// ---------------- scratch ----------------
__device__ float g_h  [Nn * F];
__device__ float g_x  [Nn * F];
__device__ float g_as [Nn * Hh];
__device__ float g_ad [Nn * Hh];
__device__ float g_al [ET * Hh];      // logits -> alpha in place
__device__ int   g_deg [Nn];
__device__ int   g_row [Nn];
__device__ int   g_cur [Nn];
__device__ int   g_csr [ET];
__device__ int   g_bsum[256];

__device__ __forceinline__ void edge_sd(int e, const int* __restrict__ ei,
                                        int& s, int& d) {
    if (e < Ee) { s = ei[e]; d = ei[Ee + e]; }
    else        { s = e - Ee; d = e - Ee; }
}

// ---------------- CSR build ----------------
__global__ void k_zero() {
    int i = blockIdx.x * blockDim.x + threadIdx.x;
    if (i < Nn) g_deg[i] = 0;
}

__global__ void k_deg(const int* __restrict__ ei) {
    int e = blockIdx.x * blockDim.x + threadIdx.x;
    if (e >= ET) return;
    int s, d; edge_sd(e, ei, s, d);
    atomicAdd(&g_deg[d], 1);
}

__global__ void k_scan_block() {
    __shared__ int sh[256];
    int tid = threadIdx.x;
    int i = blockIdx.x * 256 + tid;
    int v = (i < Nn) ? g_deg[i] : 0;
    sh[tid] = v;
    __syncthreads();
#pragma unroll
    for (int off = 1; off < 256; off <<= 1) {
        int t2 = (tid >= off) ? sh[tid - off] : 0;
        __syncthreads();
        sh[tid] += t2;
        __syncthreads();
    }
    if (i < Nn) g_row[i] = sh[tid];
    if (tid == 255) g_bsum[blockIdx.x] = sh[255];
}

__global__ void k_scan_top() {
    __shared__ int sh[256];
    int tid = threadIdx.x;
    int v = (tid < NBLK) ? g_bsum[tid] : 0;
    sh[tid] = v;
    __syncthreads();
#pragma unroll
    for (int off = 1; off < 256; off <<= 1) {
        int t2 = (tid >= off) ? sh[tid - off] : 0;
        __syncthreads();
        sh[tid] += t2;
        __syncthreads();
    }
    g_bsum[tid] = sh[tid] - v;
}

__global__ void k_scan_fix() {
    int i = blockIdx.x * blockDim.x + threadIdx.x;
    if (i >= Nn) return;
    int ro = g_row[i] - g_deg[i] + g_bsum[i >> 8];
    g_row[i] = ro;
    g_cur[i] = ro;
}

__global__ void k_fill(const int* __restrict__ ei) {
    int e = blockIdx.x * blockDim.x + threadIdx.x;
    if (e >= ET) return;
    int s, d; edge_sd(e, ei, s, d);
    int pos = atomicAdd(&g_cur[d], 1);
    g_csr[pos] = e;
}

// ---------------- per-layer kernels ----------------
// use_gx != 0 -> read the previous layer's output from the device global g_x
// (resolved DEVICE-SIDE; passing g_x from host code passes the host shadow
// symbol, which on GB300/ATS silently reads host zeros -- the R1-R6 bug).
template <int K>
__global__ void k_gemm(const float* __restrict__ xparam,
                       const float* __restrict__ W, int use_gx) {
    __shared__ float sW[F][K + 1];
    const float* __restrict__ xin = use_gx ? (const float*)g_x : xparam;
    const int tid = threadIdx.x;
    for (int i = tid; i < F * K; i += 256) sW[i / K][i % K] = W[i];
    __syncthreads();
    const int o = tid & 63, ns = tid >> 6, base = blockIdx.x * 16;
#pragma unroll
    for (int rep = 0; rep < 4; rep++) {
        const int n = base + rep * 4 + ns;
        const float* __restrict__ xr = xin + (size_t)n * K;
        float a = 0.f;
#pragma unroll
        for (int k = 0; k < K; k++) a = fmaf(__ldg(xr + k), sW[o][k], a);
        g_h[n * F + o] = a;
    }
}

__global__ void k_attdot(const float* __restrict__ att_s, const float* __restrict__ att_d) {
    int t = blockIdx.x * blockDim.x + threadIdx.x;
    if (t >= Nn * Hh) return;
    int n = t >> 2, h = t & 3;
    float vs = 0.f, vd = 0.f;
#pragma unroll
    for (int c = 0; c < Cc; c++) {
        float hv = g_h[n * F + h * Cc + c];
        vs = fmaf(hv, att_s[h * Cc + c], vs);
        vd = fmaf(hv, att_d[h * Cc + c], vd);
    }
    g_as[t] = vs;
    g_ad[t] = vd;
}

__global__ void k_logits(const int* __restrict__ ei) {
    int t = blockIdx.x * blockDim.x + threadIdx.x;
    if (t >= ET * Hh) return;
    int e = t >> 2, h = t & 3;
    int s, d; edge_sd(e, ei, s, d);
    float lg = g_as[s * Hh + h] + g_ad[d * Hh + h];
    g_al[t] = lg > 0.f ? lg : NEG * lg;
}

__global__ void k_softmax(float* __restrict__ alpha_out) {
    int t = blockIdx.x * blockDim.x + threadIdx.x;
    if (t >= Nn * Hh) return;
    int n = t >> 2, h = t & 3;
    int ro = g_row[n], dg = g_deg[n];
    float m = -1e30f;
    for (int i = 0; i < dg; i++) {
        float l = g_al[g_csr[ro + i] * Hh + h];
        m = fmaxf(m, l);
    }
    float z = 0.f;
    for (int i = 0; i < dg; i++) {
        int idx = g_csr[ro + i] * Hh + h;
        float ev = expf(g_al[idx] - m);
        g_al[idx] = ev;
        z += ev;
    }
    float inv = 1.f / z;
    for (int i = 0; i < dg; i++) {
        int idx = g_csr[ro + i] * Hh + h;
        float a = g_al[idx] * inv;
        g_al[idx] = a;
        if (alpha_out) alpha_out[idx] = a;
    }
}

__global__ void k_aggpost(const int* __restrict__ ei,
                          const float* __restrict__ bias, const float* __restrict__ gamma,
                          const float* __restrict__ beta, const float* __restrict__ mu,
                          const float* __restrict__ var) {
    int warp = (blockIdx.x * blockDim.x + threadIdx.x) >> 5;
    if (warp >= Nn) return;
    int lane = threadIdx.x & 31;
    int o1 = lane, o2 = lane + 32;
    int ro = g_row[warp], dg = g_deg[warp];
    float a1 = 0.f, a2 = 0.f;
    for (int i = 0; i < dg; i++) {
        int e = g_csr[ro + i];
        int s = (e < Ee) ? __ldg(ei + e) : (e - Ee);
        float al1 = g_al[e * Hh + (o1 >> 4)];
        float al2 = g_al[e * Hh + (o2 >> 4)];
        const float* __restrict__ hp = g_h + (size_t)s * F;
        a1 = fmaf(al1, hp[o1], a1);
        a2 = fmaf(al2, hp[o2], a2);
    }
    float v1 = fmaxf(a1 + bias[o1], 0.f);
    v1 = gamma[o1] * (v1 - mu[o1]) * rsqrtf(var[o1] + EPSbn) + beta[o1];
    g_x[warp * F + o1] = v1;
    float v2 = fmaxf(a2 + bias[o2], 0.f);
    v2 = gamma[o2] * (v2 - mu[o2]) * rsqrtf(var[o2] + EPSbn) + beta[o2];
    g_x[warp * F + o2] = v2;
}

// ---------------- head: pool + FC + sigmoid ----------------
__global__ void k_head(const int* __restrict__ batch,
                       const float* __restrict__ fcW, const float* __restrict__ fcb,
                       float* __restrict__ out) {
    __shared__ float sh[F];
    int g = blockIdx.x;         // 0..127
    int c = threadIdx.x;        // 0..63
    int lo = 0, hi = Nn;
    while (lo < hi) { int m = (lo + hi) >> 1; if (batch[m] < g) lo = m + 1; else hi = m; }
    int r0 = lo;
    lo = 0; hi = Nn;
    while (lo < hi) { int m = (lo + hi) >> 1; if (batch[m] < g + 1) lo = m + 1; else hi = m; }
    int r1 = lo;

    float acc = 0.f;
    for (int n = r0; n < r1; n++) acc += g_x[n * F + c];
    float cnt = fmaxf((float)(r1 - r0), 1.f);
    sh[c] = (acc / cnt) * fcW[c];
    __syncthreads();
    if (c == 0) {
        float z = fcb[0];
        for (int i = 0; i < F; i++) z += sh[i];
        out[g] = 1.f / (1.f + expf(-z));
    }
}

// ---------------- launch ----------------
extern "C" void kernel_launch(void* const* d_in, const int* in_sizes, int n_in,
                              void* d_out, int out_size) {
    const float* x     = (const float*)d_in[0];
    const int*   ei    = (const int*)  d_in[1];
    const int*   batch = (const int*)  d_in[2];
    const float* P[3][8];
    for (int l = 0; l < 3; l++)
        for (int j = 0; j < 8; j++)
            P[l][j] = (const float*)d_in[3 + l * 8 + j];
    const float* fcW = (const float*)d_in[27];
    const float* fcb = (const float*)d_in[28];

    float* out = (float*)d_out;
    float* alpha_out = (out_size >= NGr + ET * Hh) ? (out + NGr) : nullptr;

    const int TB = 256;
    const int gNode  = (Nn + TB - 1) / TB;
    const int gEdge  = (ET + TB - 1) / TB;
    const int gEdgeH = (ET * Hh + TB - 1) / TB;
    const int gNH    = (Nn * Hh + TB - 1) / TB;
    const int gWarp  = Nn / 8;
    const int gGemm  = Nn / 16;

    // CSR build (once)
    k_zero<<<gNode, TB>>>();
    k_deg<<<gEdge, TB>>>(ei);
    k_scan_block<<<NBLK, 256>>>();
    k_scan_top<<<1, 256>>>();
    k_scan_fix<<<gNode, TB>>>();
    k_fill<<<gEdge, TB>>>(ei);

    for (int l = 0; l < 3; l++) {
        if (l == 0) k_gemm<IND><<<gGemm, TB>>>(x, P[0][0], 0);
        else        k_gemm<F>  <<<gGemm, TB>>>(x, P[l][0], 1);  // reads g_x device-side
        k_attdot<<<gNH, TB>>>(P[l][1], P[l][2]);
        k_logits<<<gEdgeH, TB>>>(ei);
        k_softmax<<<gNH, TB>>>(l == 0 ? alpha_out : nullptr);
        k_aggpost<<<gWarp, TB>>>(ei, P[l][3], P[l][4], P[l][5], P[l][6], P[l][7]);
    }
    k_head<<<NGr, F>>>(batch, fcW, fcb, out);
}

// round 8
// speedup vs baseline: 2.0269x; 2.0269x over previous
#include <cuda_runtime.h>
#include <math.h>

// ---------------- problem constants ----------------
constexpr int Nn  = 50000;
constexpr int Ee  = 800000;
constexpr int ET  = Ee + Nn;          // 850000
constexpr int Hh  = 4;
constexpr int Cc  = 16;
constexpr int F   = Hh * Cc;          // 64
constexpr int IND = 128;
constexpr int NGr = 128;
constexpr float NEG   = 0.2f;
constexpr float EPSbn = 1e-5f;
constexpr int NBLK = (Nn + 255) / 256;  // 196 scan blocks
constexpr int GNB  = 80;                // gemm nodes per block (50000/80=625)

// ---------------- scratch ----------------
__device__ float g_h  [Nn * F];
__device__ float g_x  [Nn * F];
__device__ float g_as [Nn * Hh];      // viewed as float4[Nn]
__device__ float g_ad [Nn * Hh];
__device__ float g_al [ET * Hh];      // e-values by CSR position, float4[ET]
__device__ int   g_deg [Nn];
__device__ int   g_row [Nn];
__device__ int   g_cur [Nn];
__device__ int   g_csr [ET];          // edge id by CSR position
__device__ int   g_srcn[ET];          // src node by CSR position
__device__ int   g_bsum[256];

__device__ __forceinline__ void edge_sd(int e, const int* __restrict__ ei,
                                        int& s, int& d) {
    if (e < Ee) { s = ei[e]; d = ei[Ee + e]; }
    else        { s = e - Ee; d = e - Ee; }
}

// ---------------- CSR build ----------------
__global__ void k_zero() {
    int i = blockIdx.x * blockDim.x + threadIdx.x;
    if (i < Nn) g_deg[i] = 0;
}

__global__ void k_deg(const int* __restrict__ ei) {
    int e = blockIdx.x * blockDim.x + threadIdx.x;
    if (e >= ET) return;
    int s, d; edge_sd(e, ei, s, d);
    atomicAdd(&g_deg[d], 1);
}

__global__ void k_scan_block() {
    __shared__ int sh[256];
    int tid = threadIdx.x;
    int i = blockIdx.x * 256 + tid;
    int v = (i < Nn) ? g_deg[i] : 0;
    sh[tid] = v;
    __syncthreads();
#pragma unroll
    for (int off = 1; off < 256; off <<= 1) {
        int t2 = (tid >= off) ? sh[tid - off] : 0;
        __syncthreads();
        sh[tid] += t2;
        __syncthreads();
    }
    if (i < Nn) g_row[i] = sh[tid];
    if (tid == 255) g_bsum[blockIdx.x] = sh[255];
}

__global__ void k_scan_top() {
    __shared__ int sh[256];
    int tid = threadIdx.x;
    int v = (tid < NBLK) ? g_bsum[tid] : 0;
    sh[tid] = v;
    __syncthreads();
#pragma unroll
    for (int off = 1; off < 256; off <<= 1) {
        int t2 = (tid >= off) ? sh[tid - off] : 0;
        __syncthreads();
        sh[tid] += t2;
        __syncthreads();
    }
    g_bsum[tid] = sh[tid] - v;
}

__global__ void k_scan_fix() {
    int i = blockIdx.x * blockDim.x + threadIdx.x;
    if (i >= Nn) return;
    int ro = g_row[i] - g_deg[i] + g_bsum[i >> 8];
    g_row[i] = ro;
    g_cur[i] = ro;
}

__global__ void k_fill(const int* __restrict__ ei) {
    int e = blockIdx.x * blockDim.x + threadIdx.x;
    if (e >= ET) return;
    int s, d; edge_sd(e, ei, s, d);
    int pos = atomicAdd(&g_cur[d], 1);
    g_csr[pos]  = e;
    g_srcn[pos] = s;
}

// ---------------- GEMM: h = x @ W^T, smem-staged, register tiled ----------------
// 256 threads, GNB(=80) nodes/block. Thread (oq=tid&15, ng=tid>>4) computes
// outputs {oq,oq+16,oq+32,oq+48} for nodes {ng*5..ng*5+4}.
template <int K>
__global__ void k_gemm(const float* __restrict__ xparam,
                       const float* __restrict__ W, int use_gx) {
    extern __shared__ float smem[];
    float (*sW)[K + 1] = (float(*)[K + 1])smem;
    float (*sX)[K + 1] = (float(*)[K + 1])(smem + F * (K + 1));
    const float* __restrict__ xin = use_gx ? (const float*)g_x : xparam;
    const int tid = threadIdx.x;
    const int base = blockIdx.x * GNB;

    for (int i = tid; i < F * K / 4; i += 256) {
        float4 w = ((const float4*)W)[i];
        int f = i * 4, r = f / K, c = f % K;
        sW[r][c] = w.x; sW[r][c + 1] = w.y; sW[r][c + 2] = w.z; sW[r][c + 3] = w.w;
    }
    const float4* __restrict__ xv = (const float4*)(xin + (size_t)base * K);
    for (int i = tid; i < GNB * K / 4; i += 256) {
        float4 v = xv[i];
        int f = i * 4, r = f / K, c = f % K;
        sX[r][c] = v.x; sX[r][c + 1] = v.y; sX[r][c + 2] = v.z; sX[r][c + 3] = v.w;
    }
    __syncthreads();

    const int oq = tid & 15, ng = tid >> 4;
    float acc[4][5];
#pragma unroll
    for (int j = 0; j < 4; j++)
#pragma unroll
        for (int i = 0; i < 5; i++) acc[j][i] = 0.f;

    for (int k = 0; k < K; k++) {
        float w0 = sW[oq][k], w1 = sW[oq + 16][k];
        float w2 = sW[oq + 32][k], w3 = sW[oq + 48][k];
#pragma unroll
        for (int i = 0; i < 5; i++) {
            float xk = sX[ng * 5 + i][k];
            acc[0][i] = fmaf(w0, xk, acc[0][i]);
            acc[1][i] = fmaf(w1, xk, acc[1][i]);
            acc[2][i] = fmaf(w2, xk, acc[2][i]);
            acc[3][i] = fmaf(w3, xk, acc[3][i]);
        }
    }
#pragma unroll
    for (int i = 0; i < 5; i++)
#pragma unroll
        for (int j = 0; j < 4; j++)
            g_h[(size_t)(base + ng * 5 + i) * F + oq + 16 * j] = acc[j][i];
}

// ---------------- per-node attention dots ----------------
__global__ void k_attdot(const float* __restrict__ att_s, const float* __restrict__ att_d) {
    int t = blockIdx.x * blockDim.x + threadIdx.x;
    if (t >= Nn * Hh) return;
    int n = t >> 2, h = t & 3;
    float vs = 0.f, vd = 0.f;
#pragma unroll
    for (int c = 0; c < Cc; c++) {
        float hv = g_h[n * F + h * Cc + c];
        vs = fmaf(hv, att_s[h * Cc + c], vs);
        vd = fmaf(hv, att_d[h * Cc + c], vd);
    }
    g_as[t] = vs;
    g_ad[t] = vd;
}

// ---------------- fused edge pipeline: logits+softmax+agg+BN ----------------
// One warp per dst node. g_al holds per-CSR-position float4 (4 heads).
__global__ void k_layer(float4* __restrict__ alpha_out,
                        const float* __restrict__ bias, const float* __restrict__ gamma,
                        const float* __restrict__ beta, const float* __restrict__ mu,
                        const float* __restrict__ var) {
    int node = (blockIdx.x * blockDim.x + threadIdx.x) >> 5;
    int lane = threadIdx.x & 31;
    int ro = g_row[node], dg = g_deg[node];
    const float4* __restrict__ as4 = (const float4*)g_as;
    float4* __restrict__ al4 = (float4*)g_al;
    float4 ad = ((const float4*)g_ad)[node];

    // phase A: logits -> g_al (coalesced, CSR order), per-head max
    float m0 = -1e30f, m1 = -1e30f, m2 = -1e30f, m3 = -1e30f;
    for (int i = lane; i < dg; i += 32) {
        int s = g_srcn[ro + i];
        float4 as = as4[s];
        float l0 = as.x + ad.x; l0 = l0 > 0.f ? l0 : NEG * l0;
        float l1 = as.y + ad.y; l1 = l1 > 0.f ? l1 : NEG * l1;
        float l2 = as.z + ad.z; l2 = l2 > 0.f ? l2 : NEG * l2;
        float l3 = as.w + ad.w; l3 = l3 > 0.f ? l3 : NEG * l3;
        al4[ro + i] = make_float4(l0, l1, l2, l3);
        m0 = fmaxf(m0, l0); m1 = fmaxf(m1, l1);
        m2 = fmaxf(m2, l2); m3 = fmaxf(m3, l3);
    }
#pragma unroll
    for (int off = 16; off; off >>= 1) {
        m0 = fmaxf(m0, __shfl_xor_sync(0xffffffffu, m0, off));
        m1 = fmaxf(m1, __shfl_xor_sync(0xffffffffu, m1, off));
        m2 = fmaxf(m2, __shfl_xor_sync(0xffffffffu, m2, off));
        m3 = fmaxf(m3, __shfl_xor_sync(0xffffffffu, m3, off));
    }
    __syncwarp();
    // phase A2: exp in place, per-head sum
    float z0 = 0.f, z1 = 0.f, z2 = 0.f, z3 = 0.f;
    for (int i = lane; i < dg; i += 32) {
        float4 l = al4[ro + i];
        float e0 = __expf(l.x - m0), e1 = __expf(l.y - m1);
        float e2 = __expf(l.z - m2), e3 = __expf(l.w - m3);
        al4[ro + i] = make_float4(e0, e1, e2, e3);
        z0 += e0; z1 += e1; z2 += e2; z3 += e3;
    }
#pragma unroll
    for (int off = 16; off; off >>= 1) {
        z0 += __shfl_xor_sync(0xffffffffu, z0, off);
        z1 += __shfl_xor_sync(0xffffffffu, z1, off);
        z2 += __shfl_xor_sync(0xffffffffu, z2, off);
        z3 += __shfl_xor_sync(0xffffffffu, z3, off);
    }
    float i0 = 1.f / z0, i1 = 1.f / z1, i2 = 1.f / z2, i3 = 1.f / z3;
    __syncwarp();

    if (alpha_out) {   // layer 0 only: write normalized alphas by edge id
        for (int i = lane; i < dg; i += 32) {
            int e = g_csr[ro + i];
            float4 ev = al4[ro + i];
            alpha_out[e] = make_float4(ev.x * i0, ev.y * i1, ev.z * i2, ev.w * i3);
        }
    }

    // phase B: aggregate (unnormalized e, normalize at the end)
    int hsel = lane >> 4;                    // head of o1 (0/1); o2 head = hsel+2
    float inv1 = hsel ? i1 : i0;
    float inv2 = hsel ? i3 : i2;
    float a1 = 0.f, a2 = 0.f;
    for (int i = 0; i < dg; i++) {
        int s = g_srcn[ro + i];              // broadcast
        float4 ev = al4[ro + i];             // broadcast
        float al1 = hsel ? ev.y : ev.x;
        float al2 = hsel ? ev.w : ev.z;
        const float* __restrict__ hp = g_h + (size_t)s * F;
        a1 = fmaf(al1, hp[lane], a1);
        a2 = fmaf(al2, hp[lane + 32], a2);
    }
    a1 *= inv1; a2 *= inv2;

    int o1 = lane, o2 = lane + 32;
    float v1 = fmaxf(a1 + bias[o1], 0.f);
    v1 = gamma[o1] * (v1 - mu[o1]) * rsqrtf(var[o1] + EPSbn) + beta[o1];
    g_x[(size_t)node * F + o1] = v1;
    float v2 = fmaxf(a2 + bias[o2], 0.f);
    v2 = gamma[o2] * (v2 - mu[o2]) * rsqrtf(var[o2] + EPSbn) + beta[o2];
    g_x[(size_t)node * F + o2] = v2;
}

// ---------------- head: pool + FC + sigmoid ----------------
__global__ void k_head(const int* __restrict__ batch,
                       const float* __restrict__ fcW, const float* __restrict__ fcb,
                       float* __restrict__ out) {
    __shared__ float sh[F];
    int g = blockIdx.x;
    int c = threadIdx.x;
    int lo = 0, hi = Nn;
    while (lo < hi) { int m = (lo + hi) >> 1; if (batch[m] < g) lo = m + 1; else hi = m; }
    int r0 = lo;
    lo = 0; hi = Nn;
    while (lo < hi) { int m = (lo + hi) >> 1; if (batch[m] < g + 1) lo = m + 1; else hi = m; }
    int r1 = lo;

    float acc = 0.f;
    for (int n = r0; n < r1; n++) acc += g_x[n * F + c];
    float cnt = fmaxf((float)(r1 - r0), 1.f);
    sh[c] = (acc / cnt) * fcW[c];
    __syncthreads();
    if (c == 0) {
        float z = fcb[0];
        for (int i = 0; i < F; i++) z += sh[i];
        out[g] = 1.f / (1.f + expf(-z));
    }
}

// ---------------- launch ----------------
extern "C" void kernel_launch(void* const* d_in, const int* in_sizes, int n_in,
                              void* d_out, int out_size) {
    const float* x     = (const float*)d_in[0];
    const int*   ei    = (const int*)  d_in[1];
    const int*   batch = (const int*)  d_in[2];
    const float* P[3][8];
    for (int l = 0; l < 3; l++)
        for (int j = 0; j < 8; j++)
            P[l][j] = (const float*)d_in[3 + l * 8 + j];
    const float* fcW = (const float*)d_in[27];
    const float* fcb = (const float*)d_in[28];

    float* out = (float*)d_out;
    float4* alpha_out = (out_size >= NGr + ET * Hh) ? (float4*)(out + NGr) : nullptr;

    const int TB = 256;
    const int gNode  = (Nn + TB - 1) / TB;
    const int gEdge  = (ET + TB - 1) / TB;
    const int gLayer = Nn / 8;                 // warp per node, 8 warps/block
    const int gNH    = (Nn * Hh + TB - 1) / TB;
    const int gGemm  = Nn / GNB;               // 625

    const int smem0 = (F + GNB) * (IND + 1) * sizeof(float);  // 74.3 KB
    const int smem1 = (F + GNB) * (F + 1) * sizeof(float);    // 37.4 KB
    cudaFuncSetAttribute(k_gemm<IND>, cudaFuncAttributeMaxDynamicSharedMemorySize, smem0);
    cudaFuncSetAttribute(k_gemm<F>,   cudaFuncAttributeMaxDynamicSharedMemorySize, smem1);

    // CSR build (once)
    k_zero<<<gNode, TB>>>();
    k_deg<<<gEdge, TB>>>(ei);
    k_scan_block<<<NBLK, 256>>>();
    k_scan_top<<<1, 256>>>();
    k_scan_fix<<<gNode, TB>>>();
    k_fill<<<gEdge, TB>>>(ei);

    for (int l = 0; l < 3; l++) {
        if (l == 0) k_gemm<IND><<<gGemm, TB, smem0>>>(x, P[0][0], 0);
        else        k_gemm<F>  <<<gGemm, TB, smem1>>>(x, P[l][0], 1);
        k_attdot<<<gNH, TB>>>(P[l][1], P[l][2]);
        k_layer<<<gLayer, TB>>>(l == 0 ? alpha_out : nullptr,
                                P[l][3], P[l][4], P[l][5], P[l][6], P[l][7]);
    }
    k_head<<<NGr, F>>>(batch, fcW, fcb, out);
}